// round 1
// baseline (speedup 1.0000x reference)
#include <cuda_runtime.h>
#include <cstdint>
#include <cstdio>

#define D 64
#define NNODES 16384
#define NE 32768
#define NG 256
#define TPQ 12
#define NT (NG * TPQ)   // 3072

// ---------------- scratch (static device allocations) ----------------
__device__ float g_ew[(size_t)NE * (D * D)];   // 512 MB
__device__ float g_hidden[NE * D];
__device__ float g_x[NNODES * D];              // out == h (they coincide every iteration)
__device__ float g_agg[NNODES * D];
__device__ float g_m[NNODES * D];
__device__ float g_gi[NNODES * 3 * D];
__device__ float g_gh[NNODES * 3 * D];
__device__ float g_deg[NNODES];
__device__ float g_rootT[D * D];
__device__ float g_s2s_wihT[128 * 256];
__device__ float g_s2s_whhT[64 * 256];
__device__ float g_mem_wihT[128 * 256];
__device__ float g_lin1T[320 * 64];
__device__ float g_qstar[NG * 2 * D];
__device__ float g_hs[NG * D];
__device__ float g_cs[NG * D];
__device__ float g_hx[NG * D];

__device__ __forceinline__ float sigf(float x) { return 1.0f / (1.0f + expf(-x)); }

// ---------------- utility kernels ----------------
__global__ void k_zero(float* p, int n) {
    int i = blockIdx.x * blockDim.x + threadIdx.x;
    if (i < n) p[i] = 0.0f;
}

__global__ void k_transpose(const float* __restrict__ in, float* __restrict__ out, int R, int C) {
    int i = blockIdx.x * blockDim.x + threadIdx.x;
    if (i < R * C) {
        int r = i / C, c = i % C;
        out[c * R + r] = in[i];
    }
}

// out = relu(x @ lin0_w^T + b), x [N,3], w [64,3]
__global__ void k_lin0(const float* __restrict__ x, const float* __restrict__ w,
                       const float* __restrict__ b, float* __restrict__ out) {
    int i = blockIdx.x * blockDim.x + threadIdx.x;
    if (i >= NNODES * D) return;
    int n = i >> 6, o = i & 63;
    float v = b[o] + x[n * 3 + 0] * w[o * 3 + 0] + x[n * 3 + 1] * w[o * 3 + 1] +
              x[n * 3 + 2] * w[o * 3 + 2];
    out[i] = fmaxf(v, 0.0f);
}

// hidden = relu(edge_attr @ e1_w^T + e1_b), edge_attr [E,6], w [64,6]
__global__ void k_hidden(const float* __restrict__ ea, const float* __restrict__ w,
                         const float* __restrict__ b, float* __restrict__ out) {
    int i = blockIdx.x * blockDim.x + threadIdx.x;
    if (i >= NE * D) return;
    int e = i >> 6, j = i & 63;
    float v = b[j];
#pragma unroll
    for (int k = 0; k < 6; k++) v += ea[e * 6 + k] * w[j * 6 + k];
    out[i] = fmaxf(v, 0.0f);
}

__global__ void k_deg(const int* __restrict__ eidx, float* __restrict__ deg) {
    int e = blockIdx.x * blockDim.x + threadIdx.x;
    if (e < NE) atomicAdd(&deg[eidx[NE + e]], 1.0f);
}

// ---------------- generic K=64 GEMM: C[M,Ncols] = A[M,64] @ B[Ncols,64]^T + bias ----------------
// epi==1: conv epilogue (Ncols==64): C = relu(C + agg/deg)
__global__ void k_gemm64(const float* __restrict__ A, const float* __restrict__ B,
                         const float* __restrict__ bias, float* __restrict__ C,
                         int Ncols, int epi, const float* __restrict__ agg,
                         const float* __restrict__ deg) {
    __shared__ float As[64 * 65];
    __shared__ float Bs[64 * 65];
    int t = threadIdx.x;
    int m0 = blockIdx.y << 6, n0 = blockIdx.x << 6;
    int r = t >> 4, c4 = (t & 15) << 2;
#pragma unroll
    for (int rr = 0; rr < 64; rr += 16) {
        float4 va = *(const float4*)(A + (size_t)(m0 + r + rr) * 64 + c4);
        As[(r + rr) * 65 + c4 + 0] = va.x;
        As[(r + rr) * 65 + c4 + 1] = va.y;
        As[(r + rr) * 65 + c4 + 2] = va.z;
        As[(r + rr) * 65 + c4 + 3] = va.w;
        float4 vb = *(const float4*)(B + (size_t)(n0 + r + rr) * 64 + c4);
        Bs[(r + rr) * 65 + c4 + 0] = vb.x;
        Bs[(r + rr) * 65 + c4 + 1] = vb.y;
        Bs[(r + rr) * 65 + c4 + 2] = vb.z;
        Bs[(r + rr) * 65 + c4 + 3] = vb.w;
    }
    __syncthreads();
    int tn = (t & 15) << 2;  // 16 distinct per warp (2-way LDS conflict w/ 65 pad)
    int tm = (t >> 4) << 2;  // broadcast-friendly
    float acc[4][4] = {};
#pragma unroll 8
    for (int k = 0; k < 64; k++) {
        float a0 = As[(tm + 0) * 65 + k];
        float a1 = As[(tm + 1) * 65 + k];
        float a2 = As[(tm + 2) * 65 + k];
        float a3 = As[(tm + 3) * 65 + k];
        float b0 = Bs[(tn + 0) * 65 + k];
        float b1 = Bs[(tn + 1) * 65 + k];
        float b2 = Bs[(tn + 2) * 65 + k];
        float b3 = Bs[(tn + 3) * 65 + k];
        acc[0][0] += a0 * b0; acc[0][1] += a0 * b1; acc[0][2] += a0 * b2; acc[0][3] += a0 * b3;
        acc[1][0] += a1 * b0; acc[1][1] += a1 * b1; acc[1][2] += a1 * b2; acc[1][3] += a1 * b3;
        acc[2][0] += a2 * b0; acc[2][1] += a2 * b1; acc[2][2] += a2 * b2; acc[2][3] += a2 * b3;
        acc[3][0] += a3 * b0; acc[3][1] += a3 * b1; acc[3][2] += a3 * b2; acc[3][3] += a3 * b3;
    }
#pragma unroll
    for (int i = 0; i < 4; i++) {
        int gm = m0 + tm + i;
        float vals[4];
#pragma unroll
        for (int j = 0; j < 4; j++) {
            float v = acc[i][j] + bias[n0 + tn + j];
            if (epi == 1) {
                v += agg[(size_t)gm * 64 + n0 + tn + j] * (1.0f / fmaxf(deg[gm], 1.0f));
                v = fmaxf(v, 0.0f);
            }
            vals[j] = v;
        }
        *(float4*)(C + (size_t)gm * Ncols + n0 + tn) =
            make_float4(vals[0], vals[1], vals[2], vals[3]);
    }
}

// ---------------- per-edge einsum + scatter: agg[dst] += out[src] @ ew[e] ----------------
__global__ void k_msg(const float* __restrict__ x, const int* __restrict__ eidx,
                      const float* __restrict__ ew, float* __restrict__ agg) {
    int w = threadIdx.x >> 5, lane = threadIdx.x & 31;
    int e = blockIdx.x * 8 + w;
    int src = eidx[e], dst = eidx[NE + e];
    __shared__ float so[8][64];
    so[w][lane] = x[(size_t)src * 64 + lane];
    so[w][lane + 32] = x[(size_t)src * 64 + 32 + lane];
    __syncwarp();
    const float2* p = (const float2*)(ew + (size_t)e * 4096) + lane;
    float ax = 0.0f, ay = 0.0f;
#pragma unroll 16
    for (int i = 0; i < 64; i++) {
        float s = so[w][i];
        float2 v = p[i * 32];
        ax += s * v.x;
        ay += s * v.y;
    }
    atomicAdd(&agg[(size_t)dst * 64 + 2 * lane], ax);
    atomicAdd(&agg[(size_t)dst * 64 + 2 * lane + 1], ay);
}

// ---------------- GRU elementwise update (in place on x == h == out) ----------------
__global__ void k_gru(const float* __restrict__ gi, const float* __restrict__ gh,
                      float* __restrict__ x) {
    int i = blockIdx.x * blockDim.x + threadIdx.x;
    if (i >= NNODES * D) return;
    int n = i >> 6, o = i & 63;
    size_t b = (size_t)n * 192;
    float r = sigf(gi[b + o] + gh[b + o]);
    float z = sigf(gi[b + 64 + o] + gh[b + 64 + o]);
    float nn = tanhf(gi[b + 128 + o] + r * gh[b + 128 + o]);
    float h = x[i];
    x[i] = (1.0f - z) * nn + z * h;
}

// ---------------- Set2Set LSTM step (per-graph block, 64 threads) ----------------
__global__ void k_s2s_lstm(const float* __restrict__ wihT, const float* __restrict__ whhT,
                           const float* __restrict__ bih, const float* __restrict__ bhh,
                           const float* __restrict__ qstar, float* __restrict__ hs,
                           float* __restrict__ cs) {
    int g = blockIdx.x, t = threadIdx.x;
    __shared__ float sq[128], sh[64];
    sq[t] = qstar[g * 128 + t];
    sq[64 + t] = qstar[g * 128 + 64 + t];
    sh[t] = hs[g * 64 + t];
    __syncthreads();
    float acc0 = bih[0 * 64 + t] + bhh[0 * 64 + t];
    float acc1 = bih[1 * 64 + t] + bhh[1 * 64 + t];
    float acc2 = bih[2 * 64 + t] + bhh[2 * 64 + t];
    float acc3 = bih[3 * 64 + t] + bhh[3 * 64 + t];
#pragma unroll 4
    for (int j = 0; j < 128; j++) {
        float q = sq[j];
        acc0 += q * wihT[j * 256 + 0 * 64 + t];
        acc1 += q * wihT[j * 256 + 1 * 64 + t];
        acc2 += q * wihT[j * 256 + 2 * 64 + t];
        acc3 += q * wihT[j * 256 + 3 * 64 + t];
    }
#pragma unroll 4
    for (int j = 0; j < 64; j++) {
        float hv = sh[j];
        acc0 += hv * whhT[j * 256 + 0 * 64 + t];
        acc1 += hv * whhT[j * 256 + 1 * 64 + t];
        acc2 += hv * whhT[j * 256 + 2 * 64 + t];
        acc3 += hv * whhT[j * 256 + 3 * 64 + t];
    }
    float c = sigf(acc1) * cs[g * 64 + t] + sigf(acc0) * tanhf(acc2);
    float h = sigf(acc3) * tanhf(c);
    cs[g * 64 + t] = c;
    hs[g * 64 + t] = h;
}

// ---------------- Set2Set attention (per-graph block, 64 threads = 64 nodes) ----------------
__global__ void k_attn(const float* __restrict__ x, const float* __restrict__ hs,
                       float* __restrict__ qstar) {
    int g = blockIdx.x, t = threadIdx.x;
    __shared__ float so[64][65];
    __shared__ float sh[64];
    __shared__ float sa[64];
    __shared__ float red[64];
    sh[t] = hs[g * 64 + t];
#pragma unroll 8
    for (int n = 0; n < 64; n++) so[n][t] = x[((size_t)g * 64 + n) * 64 + t];
    __syncthreads();
    float e = 0.0f;
#pragma unroll 8
    for (int c = 0; c < 64; c++) e += so[t][c] * sh[c];
    red[t] = e;
    __syncthreads();
    for (int s = 32; s > 0; s >>= 1) {
        if (t < s) red[t] = fmaxf(red[t], red[t + s]);
        __syncthreads();
    }
    float mx = red[0];
    __syncthreads();
    float a = expf(e - mx);
    sa[t] = a;
    red[t] = a;
    __syncthreads();
    for (int s = 32; s > 0; s >>= 1) {
        if (t < s) red[t] = red[t] + red[t + s];
        __syncthreads();
    }
    float inv = 1.0f / red[0];
    float rr = 0.0f;
#pragma unroll 8
    for (int n = 0; n < 64; n++) rr += sa[n] * so[n][t];
    qstar[g * 128 + t] = sh[t];
    qstar[g * 128 + 64 + t] = rr * inv;
}

// ---------------- memory LSTM (zero initial state), writes hx / cx ----------------
__global__ void k_mem_lstm(const float* __restrict__ wihT, const float* __restrict__ bih,
                           const float* __restrict__ bhh, const float* __restrict__ qstar,
                           float* __restrict__ hx, float* __restrict__ out, int out_size) {
    int g = blockIdx.x, t = threadIdx.x;
    __shared__ float sq[128];
    sq[t] = qstar[g * 128 + t];
    sq[64 + t] = qstar[g * 128 + 64 + t];
    __syncthreads();
    float acc0 = bih[0 * 64 + t] + bhh[0 * 64 + t];
    float acc1 = bih[1 * 64 + t] + bhh[1 * 64 + t];
    float acc2 = bih[2 * 64 + t] + bhh[2 * 64 + t];
    float acc3 = bih[3 * 64 + t] + bhh[3 * 64 + t];
#pragma unroll 4
    for (int j = 0; j < 128; j++) {
        float q = sq[j];
        acc0 += q * wihT[j * 256 + 0 * 64 + t];
        acc1 += q * wihT[j * 256 + 1 * 64 + t];
        acc2 += q * wihT[j * 256 + 2 * 64 + t];
        acc3 += q * wihT[j * 256 + 3 * 64 + t];
    }
    float c = sigf(acc0) * tanhf(acc2);  // c_prev = 0
    float h = sigf(acc3) * tanhf(c);
    hx[g * 64 + t] = h;
    int base = NT * 6;
    if (out_size >= base + 2 * NG * D) {
        out[base + g * 64 + t] = h;
        out[base + NG * D + g * 64 + t] = c;
    }
}

// ---------------- final gather + MLP (faithful permute) ----------------
__global__ void k_final(const float* __restrict__ x, const float* __restrict__ hx,
                        const int* __restrict__ nonring, const float* __restrict__ lin1T,
                        const float* __restrict__ lin1b, const float* __restrict__ lin2w,
                        const float* __restrict__ lin2b, float* __restrict__ out) {
    int r = blockIdx.x, t = threadIdx.x;
    __shared__ float feat[320];
    __shared__ float o1[64];
#pragma unroll
    for (int f = t; f < 320; f += 64) {
        int linear = r * 320 + f;
        int c = linear / (NT * 5);
        int rem = linear % (NT * 5);
        int tt = rem / 5;
        int s = rem % 5;
        float v;
        if (s == 0)
            v = hx[(tt / TPQ) * 64 + c];
        else
            v = x[(size_t)nonring[(s - 1) * NT + tt] * 64 + c];
        feat[f] = v;
    }
    __syncthreads();
    float acc = lin1b[t];
#pragma unroll 8
    for (int f = 0; f < 320; f++) acc += feat[f] * lin1T[f * 64 + t];
    o1[t] = fmaxf(acc, 0.0f);
    __syncthreads();
    if (t < 6) {
        float s = lin2b[t];
#pragma unroll 8
        for (int j = 0; j < 64; j++) s += o1[j] * lin2w[t * 64 + j];
        out[r * 6 + t] = s;
    }
}

// ---------------- host side ----------------
extern "C" void kernel_launch(void* const* d_in, const int* in_sizes, int n_in,
                              void* d_out, int out_size) {
    const float* x_in = (const float*)d_in[0];
    const float* edge_attr = (const float*)d_in[1];
    const int* edge_index = (const int*)d_in[2];
    const int* nonring = (const int*)d_in[4];
    int wb = (n_in >= 32) ? 8 : 6;  // skip num_graphs/torsion_size scalars if present
    const float* lin0_w = (const float*)d_in[wb + 0];
    const float* lin0_b = (const float*)d_in[wb + 1];
    const float* e1_w = (const float*)d_in[wb + 2];
    const float* e1_b = (const float*)d_in[wb + 3];
    const float* e2_w = (const float*)d_in[wb + 4];
    const float* e2_b = (const float*)d_in[wb + 5];
    const float* root_w = (const float*)d_in[wb + 6];
    const float* conv_b = (const float*)d_in[wb + 7];
    const float* gru_wih = (const float*)d_in[wb + 8];
    const float* gru_whh = (const float*)d_in[wb + 9];
    const float* gru_bih = (const float*)d_in[wb + 10];
    const float* gru_bhh = (const float*)d_in[wb + 11];
    const float* s2s_wih = (const float*)d_in[wb + 12];
    const float* s2s_whh = (const float*)d_in[wb + 13];
    const float* s2s_bih = (const float*)d_in[wb + 14];
    const float* s2s_bhh = (const float*)d_in[wb + 15];
    const float* mem_wih = (const float*)d_in[wb + 16];
    const float* mem_bih = (const float*)d_in[wb + 18];
    const float* mem_bhh = (const float*)d_in[wb + 19];
    const float* lin1_w = (const float*)d_in[wb + 20];
    const float* lin1_b = (const float*)d_in[wb + 21];
    const float* lin2_w = (const float*)d_in[wb + 22];
    const float* lin2_b = (const float*)d_in[wb + 23];
    float* out = (float*)d_out;

    float *ew, *hidden, *xb, *agg, *m, *gi, *gh, *deg, *rootT;
    float *s2swihT, *s2swhhT, *memwihT, *lin1T, *qstar, *hs, *cs, *hx;
    cudaGetSymbolAddress((void**)&ew, g_ew);
    cudaGetSymbolAddress((void**)&hidden, g_hidden);
    cudaGetSymbolAddress((void**)&xb, g_x);
    cudaGetSymbolAddress((void**)&agg, g_agg);
    cudaGetSymbolAddress((void**)&m, g_m);
    cudaGetSymbolAddress((void**)&gi, g_gi);
    cudaGetSymbolAddress((void**)&gh, g_gh);
    cudaGetSymbolAddress((void**)&deg, g_deg);
    cudaGetSymbolAddress((void**)&rootT, g_rootT);
    cudaGetSymbolAddress((void**)&s2swihT, g_s2s_wihT);
    cudaGetSymbolAddress((void**)&s2swhhT, g_s2s_whhT);
    cudaGetSymbolAddress((void**)&memwihT, g_mem_wihT);
    cudaGetSymbolAddress((void**)&lin1T, g_lin1T);
    cudaGetSymbolAddress((void**)&qstar, g_qstar);
    cudaGetSymbolAddress((void**)&hs, g_hs);
    cudaGetSymbolAddress((void**)&cs, g_cs);
    cudaGetSymbolAddress((void**)&hx, g_hx);

    // initial projections
    k_lin0<<<(NNODES * D + 255) / 256, 256>>>(x_in, lin0_w, lin0_b, xb);
    k_hidden<<<(NE * D + 255) / 256, 256>>>(edge_attr, e1_w, e1_b, hidden);
    k_zero<<<(NNODES + 255) / 256, 256>>>(deg, NNODES);
    k_deg<<<(NE + 255) / 256, 256>>>(edge_index, deg);
    k_transpose<<<(64 * 64 + 255) / 256, 256>>>(root_w, rootT, 64, 64);
    k_transpose<<<(256 * 128 + 255) / 256, 256>>>(s2s_wih, s2swihT, 256, 128);
    k_transpose<<<(256 * 64 + 255) / 256, 256>>>(s2s_whh, s2swhhT, 256, 64);
    k_transpose<<<(256 * 128 + 255) / 256, 256>>>(mem_wih, memwihT, 256, 128);
    k_transpose<<<(64 * 320 + 255) / 256, 256>>>(lin1_w, lin1T, 64, 320);

    // edge-conditioned weight tensor: ew[E,4096] = hidden @ e2_w^T + e2_b
    k_gemm64<<<dim3(4096 / 64, NE / 64), 256>>>(hidden, e2_w, e2_b, ew, 4096, 0, nullptr, nullptr);

    // 6 NNConv + GRU iterations
    for (int it = 0; it < 6; it++) {
        k_zero<<<(NNODES * D + 255) / 256, 256>>>(agg, NNODES * D);
        k_msg<<<NE / 8, 256>>>(xb, edge_index, ew, agg);
        k_gemm64<<<dim3(1, NNODES / 64), 256>>>(xb, rootT, conv_b, m, 64, 1, agg, deg);
        k_gemm64<<<dim3(3, NNODES / 64), 256>>>(m, gru_wih, gru_bih, gi, 192, 0, nullptr, nullptr);
        k_gemm64<<<dim3(3, NNODES / 64), 256>>>(xb, gru_whh, gru_bhh, gh, 192, 0, nullptr, nullptr);
        k_gru<<<(NNODES * D + 255) / 256, 256>>>(gi, gh, xb);
    }

    // Set2Set pooling
    k_zero<<<(NG * 128 + 255) / 256, 256>>>(qstar, NG * 128);
    k_zero<<<(NG * 64 + 255) / 256, 256>>>(hs, NG * 64);
    k_zero<<<(NG * 64 + 255) / 256, 256>>>(cs, NG * 64);
    for (int s = 0; s < 6; s++) {
        k_s2s_lstm<<<NG, 64>>>(s2swihT, s2swhhT, s2s_bih, s2s_bhh, qstar, hs, cs);
        k_attn<<<NG, 64>>>(xb, hs, qstar);
    }

    // memory LSTM + final MLP
    k_mem_lstm<<<NG, 64>>>(memwihT, mem_bih, mem_bhh, qstar, hx, out, out_size);
    k_final<<<NT, 64>>>(xb, hx, nonring, lin1T, lin1_b, lin2_w, lin2_b, out);
}

// round 5
// speedup vs baseline: 1.3872x; 1.3872x over previous
#include <cuda_runtime.h>
#include <cstdint>
#include <cstdio>

#define D 64
#define NNODES 16384
#define NE 32768
#define NG 256
#define TPQ 12
#define NT (NG * TPQ)   // 3072

// ---------------- scratch (static device allocations) ----------------
__device__ float g_ew[(size_t)NE * (D * D)];   // 512 MB
__device__ float g_hidden[NE * D];
__device__ float g_x[NNODES * D];              // out == h
__device__ float g_agg[NNODES * D];
__device__ float g_m[NNODES * D];
__device__ float g_deg[NNODES];
__device__ float g_rootT[D * D];
__device__ float g_gru_wihT[64 * 192];
__device__ float g_gru_whhT[64 * 192];
__device__ float g_s2s_wihT[128 * 256];
__device__ float g_s2s_whhT[64 * 256];
__device__ float g_mem_wihT[128 * 256];
__device__ float g_lin1T[320 * 64];
__device__ float g_qstar[NG * 2 * D];
__device__ float g_hs[NG * D];
__device__ float g_cs[NG * D];
__device__ float g_hx[NG * D];

__device__ __forceinline__ float sigf(float x) { return 1.0f / (1.0f + expf(-x)); }
__device__ __forceinline__ uint32_t f2tf32(float f) {
    uint32_t r; asm("cvt.rna.tf32.f32 %0, %1;" : "=r"(r) : "f"(f)); return r;
}

// ---------------- utility kernels ----------------
__global__ void k_zero(float* p, int n) {
    int i = blockIdx.x * blockDim.x + threadIdx.x;
    if (i < n) p[i] = 0.0f;
}

__global__ void k_transpose(const float* __restrict__ in, float* __restrict__ out, int R, int C) {
    int i = blockIdx.x * blockDim.x + threadIdx.x;
    if (i < R * C) {
        int r = i / C, c = i % C;
        out[c * R + r] = in[i];
    }
}

__global__ void k_lin0(const float* __restrict__ x, const float* __restrict__ w,
                       const float* __restrict__ b, float* __restrict__ out) {
    int i = blockIdx.x * blockDim.x + threadIdx.x;
    if (i >= NNODES * D) return;
    int n = i >> 6, o = i & 63;
    float v = b[o] + x[n * 3 + 0] * w[o * 3 + 0] + x[n * 3 + 1] * w[o * 3 + 1] +
              x[n * 3 + 2] * w[o * 3 + 2];
    out[i] = fmaxf(v, 0.0f);
}

__global__ void k_hidden(const float* __restrict__ ea, const float* __restrict__ w,
                         const float* __restrict__ b, float* __restrict__ out) {
    int i = blockIdx.x * blockDim.x + threadIdx.x;
    if (i >= NE * D) return;
    int e = i >> 6, j = i & 63;
    float v = b[j];
#pragma unroll
    for (int k = 0; k < 6; k++) v += ea[e * 6 + k] * w[j * 6 + k];
    out[i] = fmaxf(v, 0.0f);
}

__global__ void k_deg(const int* __restrict__ eidx, float* __restrict__ deg) {
    int e = blockIdx.x * blockDim.x + threadIdx.x;
    if (e < NE) atomicAdd(&deg[eidx[NE + e]], 1.0f);
}

// ---------------- tf32 MMA GEMM: ew[E,4096] = hidden[E,64] @ e2_w[4096,64]^T + b2 ------
// 64x64 tile, K=64 full, static shared (34.8KB), 256 threads = 8 warps (4m x 2n),
// warp tile 16x32 = 1 m-frag x 4 n-frags of m16n8k8.
__global__ void __launch_bounds__(256) k_ew_tf32(
    const float* __restrict__ A, const float* __restrict__ B,
    const float* __restrict__ bias, float* __restrict__ C) {
    __shared__ uint32_t As[64 * 68];
    __shared__ uint32_t Bs[64 * 68];
    int t = threadIdx.x;
    int m0 = blockIdx.y << 6, n0 = blockIdx.x << 6;
#pragma unroll
    for (int i = t; i < 1024; i += 256) {
        int r = i >> 4, c4 = (i & 15) << 2;
        float4 va = *(const float4*)(A + (size_t)(m0 + r) * 64 + c4);
        uint32_t* da = &As[r * 68 + c4];
        da[0] = f2tf32(va.x); da[1] = f2tf32(va.y); da[2] = f2tf32(va.z); da[3] = f2tf32(va.w);
        float4 vb = *(const float4*)(B + (size_t)(n0 + r) * 64 + c4);
        uint32_t* db = &Bs[r * 68 + c4];
        db[0] = f2tf32(vb.x); db[1] = f2tf32(vb.y); db[2] = f2tf32(vb.z); db[3] = f2tf32(vb.w);
    }
    __syncthreads();
    int lane = t & 31, w = t >> 5;
    int wm = (w >> 1) << 4;   // warp m offset: 0,16,32,48
    int wn = (w & 1) << 5;    // warp n offset: 0,32
    int grp = lane >> 2, tig = lane & 3;
    float acc[4][4];
#pragma unroll
    for (int a = 0; a < 4; a++)
#pragma unroll
        for (int c = 0; c < 4; c++) acc[a][c] = 0.0f;

#pragma unroll
    for (int k0 = 0; k0 < 64; k0 += 8) {
        uint32_t af[4];
        int row = wm + grp;
        af[0] = As[row * 68 + k0 + tig];
        af[1] = As[(row + 8) * 68 + k0 + tig];
        af[2] = As[row * 68 + k0 + tig + 4];
        af[3] = As[(row + 8) * 68 + k0 + tig + 4];
#pragma unroll
        for (int nt = 0; nt < 4; nt++) {
            int col = wn + (nt << 3) + grp;
            uint32_t b0 = Bs[col * 68 + k0 + tig];
            uint32_t b1 = Bs[col * 68 + k0 + tig + 4];
            asm volatile(
                "mma.sync.aligned.m16n8k8.row.col.f32.tf32.tf32.f32 "
                "{%0,%1,%2,%3}, {%4,%5,%6,%7}, {%8,%9}, {%0,%1,%2,%3};\n"
                : "+f"(acc[nt][0]), "+f"(acc[nt][1]), "+f"(acc[nt][2]), "+f"(acc[nt][3])
                : "r"(af[0]), "r"(af[1]), "r"(af[2]), "r"(af[3]), "r"(b0), "r"(b1));
        }
    }
    int row = m0 + wm + grp;
#pragma unroll
    for (int nt = 0; nt < 4; nt++) {
        int col = n0 + wn + (nt << 3) + (tig << 1);
        float b0v = bias[col], b1v = bias[col + 1];
        *(float2*)(C + (size_t)row * 4096 + col) =
            make_float2(acc[nt][0] + b0v, acc[nt][1] + b1v);
        *(float2*)(C + (size_t)(row + 8) * 4096 + col) =
            make_float2(acc[nt][2] + b0v, acc[nt][3] + b1v);
    }
}

// ---------------- generic K=64 GEMM (root conv epilogue) ----------------
__global__ void k_gemm64(const float* __restrict__ A, const float* __restrict__ B,
                         const float* __restrict__ bias, float* __restrict__ C,
                         int Ncols, int epi, const float* __restrict__ agg,
                         const float* __restrict__ deg) {
    __shared__ float As[64 * 65];
    __shared__ float Bs[64 * 65];
    int t = threadIdx.x;
    int m0 = blockIdx.y << 6, n0 = blockIdx.x << 6;
    int r = t >> 4, c4 = (t & 15) << 2;
#pragma unroll
    for (int rr = 0; rr < 64; rr += 16) {
        float4 va = *(const float4*)(A + (size_t)(m0 + r + rr) * 64 + c4);
        As[(r + rr) * 65 + c4 + 0] = va.x;
        As[(r + rr) * 65 + c4 + 1] = va.y;
        As[(r + rr) * 65 + c4 + 2] = va.z;
        As[(r + rr) * 65 + c4 + 3] = va.w;
        float4 vb = *(const float4*)(B + (size_t)(n0 + r + rr) * 64 + c4);
        Bs[(r + rr) * 65 + c4 + 0] = vb.x;
        Bs[(r + rr) * 65 + c4 + 1] = vb.y;
        Bs[(r + rr) * 65 + c4 + 2] = vb.z;
        Bs[(r + rr) * 65 + c4 + 3] = vb.w;
    }
    __syncthreads();
    int tn = (t & 15) << 2;
    int tm = (t >> 4) << 2;
    float acc[4][4] = {};
#pragma unroll 8
    for (int k = 0; k < 64; k++) {
        float a0 = As[(tm + 0) * 65 + k];
        float a1 = As[(tm + 1) * 65 + k];
        float a2 = As[(tm + 2) * 65 + k];
        float a3 = As[(tm + 3) * 65 + k];
        float b0 = Bs[(tn + 0) * 65 + k];
        float b1 = Bs[(tn + 1) * 65 + k];
        float b2 = Bs[(tn + 2) * 65 + k];
        float b3 = Bs[(tn + 3) * 65 + k];
        acc[0][0] += a0 * b0; acc[0][1] += a0 * b1; acc[0][2] += a0 * b2; acc[0][3] += a0 * b3;
        acc[1][0] += a1 * b0; acc[1][1] += a1 * b1; acc[1][2] += a1 * b2; acc[1][3] += a1 * b3;
        acc[2][0] += a2 * b0; acc[2][1] += a2 * b1; acc[2][2] += a2 * b2; acc[2][3] += a2 * b3;
        acc[3][0] += a3 * b0; acc[3][1] += a3 * b1; acc[3][2] += a3 * b2; acc[3][3] += a3 * b3;
    }
#pragma unroll
    for (int i = 0; i < 4; i++) {
        int gm = m0 + tm + i;
        float vals[4];
#pragma unroll
        for (int j = 0; j < 4; j++) {
            float v = acc[i][j] + bias[n0 + tn + j];
            if (epi == 1) {
                v += agg[(size_t)gm * 64 + n0 + tn + j] * (1.0f / fmaxf(deg[gm], 1.0f));
                v = fmaxf(v, 0.0f);
            }
            vals[j] = v;
        }
        *(float4*)(C + (size_t)gm * Ncols + n0 + tn) =
            make_float4(vals[0], vals[1], vals[2], vals[3]);
    }
}

// ---------------- per-edge einsum + scatter ----------------
__global__ void k_msg(const float* __restrict__ x, const int* __restrict__ eidx,
                      const float* __restrict__ ew, float* __restrict__ agg) {
    int w = threadIdx.x >> 5, lane = threadIdx.x & 31;
    int e = blockIdx.x * 8 + w;
    int src = eidx[e], dst = eidx[NE + e];
    __shared__ float so[8][64];
    so[w][lane] = x[(size_t)src * 64 + lane];
    so[w][lane + 32] = x[(size_t)src * 64 + 32 + lane];
    __syncwarp();
    const float2* p = (const float2*)(ew + (size_t)e * 4096) + lane;
    float ax = 0.0f, ay = 0.0f;
#pragma unroll 16
    for (int i = 0; i < 64; i++) {
        float s = so[w][i];
        float2 v = p[i * 32];
        ax += s * v.x;
        ay += s * v.y;
    }
    atomicAdd(&agg[(size_t)dst * 64 + 2 * lane], ax);
    atomicAdd(&agg[(size_t)dst * 64 + 2 * lane + 1], ay);
}

// ---------------- fused GRU ----------------
__global__ void __launch_bounds__(512, 1)
k_gru_fused(const float* __restrict__ m, const float* __restrict__ wihT,
            const float* __restrict__ whhT, const float* __restrict__ bih,
            const float* __restrict__ bhh, float* __restrict__ x) {
    __shared__ float sm[64][64];
    __shared__ float sx[64][64];
    int t = threadIdx.x;
    int n0 = blockIdx.x << 6;
    for (int i = t; i < 64 * 16; i += 512) {
        int r = i >> 4, c = (i & 15) << 2;
        *(float4*)&sm[r][c] = *(const float4*)(m + (size_t)(n0 + r) * 64 + c);
        *(float4*)&sx[r][c] = *(const float4*)(x + (size_t)(n0 + r) * 64 + c);
    }
    __syncthreads();
    int o = t & 63, grp = t >> 6;
    int nb = grp << 3;
    float a0[8] = {}, a1[8] = {}, a2[8] = {}, b0[8] = {}, b1[8] = {}, b2[8] = {};
#pragma unroll 4
    for (int k = 0; k < 64; k++) {
        float wi0 = wihT[k * 192 + o];
        float wi1 = wihT[k * 192 + 64 + o];
        float wi2 = wihT[k * 192 + 128 + o];
        float wh0 = whhT[k * 192 + o];
        float wh1 = whhT[k * 192 + 64 + o];
        float wh2 = whhT[k * 192 + 128 + o];
#pragma unroll
        for (int j = 0; j < 8; j++) {
            float mv = sm[nb + j][k];
            float xv = sx[nb + j][k];
            a0[j] += mv * wi0; a1[j] += mv * wi1; a2[j] += mv * wi2;
            b0[j] += xv * wh0; b1[j] += xv * wh1; b2[j] += xv * wh2;
        }
    }
    float bi0 = bih[o], bi1 = bih[64 + o], bi2 = bih[128 + o];
    float bh0 = bhh[o], bh1 = bhh[64 + o], bh2 = bhh[128 + o];
#pragma unroll
    for (int j = 0; j < 8; j++) {
        int n = n0 + nb + j;
        float r = sigf(a0[j] + bi0 + b0[j] + bh0);
        float z = sigf(a1[j] + bi1 + b1[j] + bh1);
        float nn = tanhf(a2[j] + bi2 + r * (b2[j] + bh2));
        float h = sx[nb + j][o];
        x[(size_t)n * 64 + o] = (1.0f - z) * nn + z * h;
    }
}

// ---------------- Set2Set LSTM step ----------------
__global__ void k_s2s_lstm(const float* __restrict__ wihT, const float* __restrict__ whhT,
                           const float* __restrict__ bih, const float* __restrict__ bhh,
                           const float* __restrict__ qstar, float* __restrict__ hs,
                           float* __restrict__ cs) {
    int g = blockIdx.x, t = threadIdx.x;
    __shared__ float sq[128], sh[64];
    sq[t] = qstar[g * 128 + t];
    sq[64 + t] = qstar[g * 128 + 64 + t];
    sh[t] = hs[g * 64 + t];
    __syncthreads();
    float acc0 = bih[0 * 64 + t] + bhh[0 * 64 + t];
    float acc1 = bih[1 * 64 + t] + bhh[1 * 64 + t];
    float acc2 = bih[2 * 64 + t] + bhh[2 * 64 + t];
    float acc3 = bih[3 * 64 + t] + bhh[3 * 64 + t];
#pragma unroll 4
    for (int j = 0; j < 128; j++) {
        float q = sq[j];
        acc0 += q * wihT[j * 256 + 0 * 64 + t];
        acc1 += q * wihT[j * 256 + 1 * 64 + t];
        acc2 += q * wihT[j * 256 + 2 * 64 + t];
        acc3 += q * wihT[j * 256 + 3 * 64 + t];
    }
#pragma unroll 4
    for (int j = 0; j < 64; j++) {
        float hv = sh[j];
        acc0 += hv * whhT[j * 256 + 0 * 64 + t];
        acc1 += hv * whhT[j * 256 + 1 * 64 + t];
        acc2 += hv * whhT[j * 256 + 2 * 64 + t];
        acc3 += hv * whhT[j * 256 + 3 * 64 + t];
    }
    float c = sigf(acc1) * cs[g * 64 + t] + sigf(acc0) * tanhf(acc2);
    float h = sigf(acc3) * tanhf(c);
    cs[g * 64 + t] = c;
    hs[g * 64 + t] = h;
}

// ---------------- Set2Set attention ----------------
__global__ void k_attn(const float* __restrict__ x, const float* __restrict__ hs,
                       float* __restrict__ qstar) {
    int g = blockIdx.x, t = threadIdx.x;
    __shared__ float so[64][65];
    __shared__ float sh[64];
    __shared__ float sa[64];
    __shared__ float red[64];
    sh[t] = hs[g * 64 + t];
#pragma unroll 8
    for (int n = 0; n < 64; n++) so[n][t] = x[((size_t)g * 64 + n) * 64 + t];
    __syncthreads();
    float e = 0.0f;
#pragma unroll 8
    for (int c = 0; c < 64; c++) e += so[t][c] * sh[c];
    red[t] = e;
    __syncthreads();
    for (int s = 32; s > 0; s >>= 1) {
        if (t < s) red[t] = fmaxf(red[t], red[t + s]);
        __syncthreads();
    }
    float mx = red[0];
    __syncthreads();
    float a = expf(e - mx);
    sa[t] = a;
    red[t] = a;
    __syncthreads();
    for (int s = 32; s > 0; s >>= 1) {
        if (t < s) red[t] = red[t] + red[t + s];
        __syncthreads();
    }
    float inv = 1.0f / red[0];
    float rr = 0.0f;
#pragma unroll 8
    for (int n = 0; n < 64; n++) rr += sa[n] * so[n][t];
    qstar[g * 128 + t] = sh[t];
    qstar[g * 128 + 64 + t] = rr * inv;
}

// ---------------- memory LSTM ----------------
__global__ void k_mem_lstm(const float* __restrict__ wihT, const float* __restrict__ bih,
                           const float* __restrict__ bhh, const float* __restrict__ qstar,
                           float* __restrict__ hx, float* __restrict__ out, int out_size) {
    int g = blockIdx.x, t = threadIdx.x;
    __shared__ float sq[128];
    sq[t] = qstar[g * 128 + t];
    sq[64 + t] = qstar[g * 128 + 64 + t];
    __syncthreads();
    float acc0 = bih[0 * 64 + t] + bhh[0 * 64 + t];
    float acc1 = bih[1 * 64 + t] + bhh[1 * 64 + t];
    float acc2 = bih[2 * 64 + t] + bhh[2 * 64 + t];
    float acc3 = bih[3 * 64 + t] + bhh[3 * 64 + t];
#pragma unroll 4
    for (int j = 0; j < 128; j++) {
        float q = sq[j];
        acc0 += q * wihT[j * 256 + 0 * 64 + t];
        acc1 += q * wihT[j * 256 + 1 * 64 + t];
        acc2 += q * wihT[j * 256 + 2 * 64 + t];
        acc3 += q * wihT[j * 256 + 3 * 64 + t];
    }
    float c = sigf(acc0) * tanhf(acc2);
    float h = sigf(acc3) * tanhf(c);
    hx[g * 64 + t] = h;
    int base = NT * 6;
    if (out_size >= base + 2 * NG * D) {
        out[base + g * 64 + t] = h;
        out[base + NG * D + g * 64 + t] = c;
    }
}

// ---------------- final gather + MLP ----------------
__global__ void k_final(const float* __restrict__ x, const float* __restrict__ hx,
                        const int* __restrict__ nonring, const float* __restrict__ lin1T,
                        const float* __restrict__ lin1b, const float* __restrict__ lin2w,
                        const float* __restrict__ lin2b, float* __restrict__ out) {
    int r = blockIdx.x, t = threadIdx.x;
    __shared__ float feat[320];
    __shared__ float o1[64];
#pragma unroll
    for (int f = t; f < 320; f += 64) {
        int linear = r * 320 + f;
        int c = linear / (NT * 5);
        int rem = linear % (NT * 5);
        int tt = rem / 5;
        int s = rem % 5;
        float v;
        if (s == 0)
            v = hx[(tt / TPQ) * 64 + c];
        else
            v = x[(size_t)nonring[(s - 1) * NT + tt] * 64 + c];
        feat[f] = v;
    }
    __syncthreads();
    float acc = lin1b[t];
#pragma unroll 8
    for (int f = 0; f < 320; f++) acc += feat[f] * lin1T[f * 64 + t];
    o1[t] = fmaxf(acc, 0.0f);
    __syncthreads();
    if (t < 6) {
        float s = lin2b[t];
#pragma unroll 8
        for (int j = 0; j < 64; j++) s += o1[j] * lin2w[t * 64 + j];
        out[r * 6 + t] = s;
    }
}

// ---------------- host side (launches ONLY — nothing else is capture-safe) ----------------
extern "C" void kernel_launch(void* const* d_in, const int* in_sizes, int n_in,
                              void* d_out, int out_size) {
    const float* x_in = (const float*)d_in[0];
    const float* edge_attr = (const float*)d_in[1];
    const int* edge_index = (const int*)d_in[2];
    const int* nonring = (const int*)d_in[4];
    int wb = (n_in >= 32) ? 8 : 6;
    const float* lin0_w = (const float*)d_in[wb + 0];
    const float* lin0_b = (const float*)d_in[wb + 1];
    const float* e1_w = (const float*)d_in[wb + 2];
    const float* e1_b = (const float*)d_in[wb + 3];
    const float* e2_w = (const float*)d_in[wb + 4];
    const float* e2_b = (const float*)d_in[wb + 5];
    const float* root_w = (const float*)d_in[wb + 6];
    const float* conv_b = (const float*)d_in[wb + 7];
    const float* gru_wih = (const float*)d_in[wb + 8];
    const float* gru_whh = (const float*)d_in[wb + 9];
    const float* gru_bih = (const float*)d_in[wb + 10];
    const float* gru_bhh = (const float*)d_in[wb + 11];
    const float* s2s_wih = (const float*)d_in[wb + 12];
    const float* s2s_whh = (const float*)d_in[wb + 13];
    const float* s2s_bih = (const float*)d_in[wb + 14];
    const float* s2s_bhh = (const float*)d_in[wb + 15];
    const float* mem_wih = (const float*)d_in[wb + 16];
    const float* mem_bih = (const float*)d_in[wb + 18];
    const float* mem_bhh = (const float*)d_in[wb + 19];
    const float* lin1_w = (const float*)d_in[wb + 20];
    const float* lin1_b = (const float*)d_in[wb + 21];
    const float* lin2_w = (const float*)d_in[wb + 22];
    const float* lin2_b = (const float*)d_in[wb + 23];
    float* out = (float*)d_out;

    float *ew, *hidden, *xb, *agg, *m, *deg, *rootT, *gruWihT, *gruWhhT;
    float *s2swihT, *s2swhhT, *memwihT, *lin1T, *qstar, *hs, *cs, *hx;
    cudaGetSymbolAddress((void**)&ew, g_ew);
    cudaGetSymbolAddress((void**)&hidden, g_hidden);
    cudaGetSymbolAddress((void**)&xb, g_x);
    cudaGetSymbolAddress((void**)&agg, g_agg);
    cudaGetSymbolAddress((void**)&m, g_m);
    cudaGetSymbolAddress((void**)&deg, g_deg);
    cudaGetSymbolAddress((void**)&rootT, g_rootT);
    cudaGetSymbolAddress((void**)&gruWihT, g_gru_wihT);
    cudaGetSymbolAddress((void**)&gruWhhT, g_gru_whhT);
    cudaGetSymbolAddress((void**)&s2swihT, g_s2s_wihT);
    cudaGetSymbolAddress((void**)&s2swhhT, g_s2s_whhT);
    cudaGetSymbolAddress((void**)&memwihT, g_mem_wihT);
    cudaGetSymbolAddress((void**)&lin1T, g_lin1T);
    cudaGetSymbolAddress((void**)&qstar, g_qstar);
    cudaGetSymbolAddress((void**)&hs, g_hs);
    cudaGetSymbolAddress((void**)&cs, g_cs);
    cudaGetSymbolAddress((void**)&hx, g_hx);

    // initial projections + weight transposes
    k_lin0<<<(NNODES * D + 255) / 256, 256>>>(x_in, lin0_w, lin0_b, xb);
    k_hidden<<<(NE * D + 255) / 256, 256>>>(edge_attr, e1_w, e1_b, hidden);
    k_zero<<<(NNODES + 255) / 256, 256>>>(deg, NNODES);
    k_deg<<<(NE + 255) / 256, 256>>>(edge_index, deg);
    k_transpose<<<(64 * 64 + 255) / 256, 256>>>(root_w, rootT, 64, 64);
    k_transpose<<<(192 * 64 + 255) / 256, 256>>>(gru_wih, gruWihT, 192, 64);
    k_transpose<<<(192 * 64 + 255) / 256, 256>>>(gru_whh, gruWhhT, 192, 64);
    k_transpose<<<(256 * 128 + 255) / 256, 256>>>(s2s_wih, s2swihT, 256, 128);
    k_transpose<<<(256 * 64 + 255) / 256, 256>>>(s2s_whh, s2swhhT, 256, 64);
    k_transpose<<<(256 * 128 + 255) / 256, 256>>>(mem_wih, memwihT, 256, 128);
    k_transpose<<<(64 * 320 + 255) / 256, 256>>>(lin1_w, lin1T, 64, 320);

    // edge-conditioned weight tensor via tf32 tensor cores (static smem, 64x64 tiles)
    k_ew_tf32<<<dim3(4096 / 64, NE / 64), 256>>>(hidden, e2_w, e2_b, ew);

    // 6 NNConv + GRU iterations
    for (int it = 0; it < 6; it++) {
        k_zero<<<(NNODES * D + 255) / 256, 256>>>(agg, NNODES * D);
        k_msg<<<NE / 8, 256>>>(xb, edge_index, ew, agg);
        k_gemm64<<<dim3(1, NNODES / 64), 256>>>(xb, rootT, conv_b, m, 64, 1, agg, deg);
        k_gru_fused<<<256, 512>>>(m, gruWihT, gruWhhT, gru_bih, gru_bhh, xb);
    }

    // Set2Set pooling
    k_zero<<<(NG * 128 + 255) / 256, 256>>>(qstar, NG * 128);
    k_zero<<<(NG * 64 + 255) / 256, 256>>>(hs, NG * 64);
    k_zero<<<(NG * 64 + 255) / 256, 256>>>(cs, NG * 64);
    for (int s = 0; s < 6; s++) {
        k_s2s_lstm<<<NG, 64>>>(s2swihT, s2swhhT, s2s_bih, s2s_bhh, qstar, hs, cs);
        k_attn<<<NG, 64>>>(xb, hs, qstar);
    }

    // memory LSTM + final MLP
    k_mem_lstm<<<NG, 64>>>(memwihT, mem_bih, mem_bhh, qstar, hx, out, out_size);
    k_final<<<NT, 64>>>(xb, hx, nonring, lin1T, lin1_b, lin2_w, lin2_b, out);
}